// round 5
// baseline (speedup 1.0000x reference)
#include <cuda_runtime.h>

#define N_CELL  50000
#define N_NET   10000
#define N_GCELL 20000
#define NE      100000
#define D       32
#define DPF     16
#define GP      17           // DPF + 1 (bias-matrix row block)
#define TSRC    16           // source nodes per fused-nnconv block
#define NB_NET_NN (N_NET / TSRC)     // 625
#define NB_GC_NN  (N_GCELL / TSRC)   // 1250

// ---------------- scratch (static device globals; no allocs) ------------
__device__ __align__(16) float g_agg_net[N_NET * D];
__device__ __align__(16) float g_agg_gc_c[N_GCELL * D];
__device__ __align__(16) float g_agg_gc_pt[N_GCELL * D];
__device__ __align__(16) float g_agg_cell_pd[N_CELL * D];
__device__ __align__(16) float g_agg_cell_pf[N_CELL * D];
__device__ __align__(16) int g_cnt_pins_src[N_CELL];
__device__ __align__(16) int g_cnt_pins_dst[N_NET];
__device__ __align__(16) int g_cnt_pinned_dst[N_CELL];
__device__ __align__(16) int g_cnt_pinned_src[N_NET];
__device__ __align__(16) int g_cnt_connect_src[N_GCELL];
__device__ __align__(16) int g_cnt_connect_dst[N_GCELL];
__device__ __align__(16) int g_cnt_pt_src[N_CELL];
__device__ __align__(16) int g_cnt_pt_dst[N_GCELL];
__device__ __align__(16) int g_cnt_pf_dst[N_CELL];
__device__ __align__(16) int g_cnt_pf_src[N_GCELL];
__device__ int g_start_net[N_NET + 1];
__device__ int g_start_han[N_GCELL + 1];
__device__ int g_cur_net[N_NET];
__device__ int g_cur_han[N_GCELL];
__device__ int g_csr_net[NE];
__device__ int g_csr_han[NE];

// vector reduction to global (sm_90+)
__device__ __forceinline__ void red_add_f4(float* p, float4 v) {
    asm volatile("red.global.add.v4.f32 [%0], {%1,%2,%3,%4};"
                 :: "l"(p), "f"(v.x), "f"(v.y), "f"(v.z), "f"(v.w) : "memory");
}

__device__ __forceinline__ unsigned cvt_tf32(float x) {
    unsigned r;
    asm("cvt.rna.tf32.f32 %0, %1;" : "=r"(r) : "f"(x));
    return r;
}

__device__ __forceinline__ void mma_tf32(float c[4],
        unsigned a0, unsigned a1, unsigned a2, unsigned a3,
        unsigned b0, unsigned b1) {
    asm("mma.sync.aligned.m16n8k8.row.col.f32.tf32.tf32.f32 "
        "{%0,%1,%2,%3}, {%4,%5,%6,%7}, {%8,%9}, {%0,%1,%2,%3};"
        : "+f"(c[0]), "+f"(c[1]), "+f"(c[2]), "+f"(c[3])
        : "r"(a0), "r"(a1), "r"(a2), "r"(a3), "r"(b0), "r"(b1));
}

// ---------------- kernels ----------------

// vectorized zero of aggs (float4) + counts (int4). All sizes /4 exact.
#define ZF4 ((N_NET*D + 2*N_GCELL*D + 2*N_CELL*D) / 4)      // 1,200,000 float4
#define ZI4 ((2*N_CELL + 2*N_NET + 4*N_GCELL + 2*N_CELL) / 4) // 60,000 int4
__global__ void k_zero() {
    int tid = blockIdx.x * blockDim.x + threadIdx.x;
    int stride = gridDim.x * blockDim.x;
    float4 z4 = {0.f, 0.f, 0.f, 0.f};
    int4 zi = {0, 0, 0, 0};
    float4* f = (float4*)g_agg_net;   // contiguity across separate symbols not guaranteed;
    // zero each array separately with grid-stride on float4 granularity
    for (int i = tid; i < N_NET * D / 4; i += stride) ((float4*)g_agg_net)[i] = z4;
    for (int i = tid; i < N_GCELL * D / 4; i += stride) { ((float4*)g_agg_gc_c)[i] = z4; ((float4*)g_agg_gc_pt)[i] = z4; }
    for (int i = tid; i < N_CELL * D / 4; i += stride) { ((float4*)g_agg_cell_pd)[i] = z4; ((float4*)g_agg_cell_pf)[i] = z4; }
    for (int i = tid; i < N_CELL / 4; i += stride) {
        ((int4*)g_cnt_pins_src)[i] = zi; ((int4*)g_cnt_pinned_dst)[i] = zi;
        ((int4*)g_cnt_pt_src)[i] = zi;   ((int4*)g_cnt_pf_dst)[i] = zi;
    }
    for (int i = tid; i < N_NET / 4; i += stride) { ((int4*)g_cnt_pins_dst)[i] = zi; ((int4*)g_cnt_pinned_src)[i] = zi; }
    for (int i = tid; i < N_GCELL / 4; i += stride) {
        ((int4*)g_cnt_connect_src)[i] = zi; ((int4*)g_cnt_connect_dst)[i] = zi;
        ((int4*)g_cnt_pt_dst)[i] = zi;      ((int4*)g_cnt_pf_src)[i] = zi;
    }
    (void)f;
}

__global__ void k_deg(const int* __restrict__ pins_src, const int* __restrict__ pins_dst,
                      const int* __restrict__ pinned_src, const int* __restrict__ pinned_dst,
                      const int* __restrict__ connect_src, const int* __restrict__ connect_dst,
                      const int* __restrict__ pt_src, const int* __restrict__ pt_dst,
                      const int* __restrict__ pf_src, const int* __restrict__ pf_dst) {
    int e = blockIdx.x * blockDim.x + threadIdx.x;
    if (e >= NE) return;
    atomicAdd(&g_cnt_pins_src[pins_src[e]], 1);
    atomicAdd(&g_cnt_pins_dst[pins_dst[e]], 1);
    atomicAdd(&g_cnt_pinned_src[pinned_src[e]], 1);
    atomicAdd(&g_cnt_pinned_dst[pinned_dst[e]], 1);
    atomicAdd(&g_cnt_connect_src[connect_src[e]], 1);
    atomicAdd(&g_cnt_connect_dst[connect_dst[e]], 1);
    atomicAdd(&g_cnt_pt_src[pt_src[e]], 1);
    atomicAdd(&g_cnt_pt_dst[pt_dst[e]], 1);
    atomicAdd(&g_cnt_pf_src[pf_src[e]], 1);
    atomicAdd(&g_cnt_pf_dst[pf_dst[e]], 1);
}

// exclusive scan of out-degree counts -> CSR row starts + fill cursors.
__global__ void k_scan() {
    const int* cnt; int* start; int* cursor; int n;
    if (blockIdx.x == 0) { cnt = g_cnt_pinned_src; start = g_start_net; cursor = g_cur_net; n = N_NET; }
    else                 { cnt = g_cnt_pf_src;     start = g_start_han; cursor = g_cur_han; n = N_GCELL; }
    int t = threadIdx.x;
    int chunk = (n + 1023) / 1024;
    int lo = t * chunk, hi = min(lo + chunk, n);
    int s = 0;
    for (int i = lo; i < hi; i++) s += cnt[i];
    __shared__ int sh[1024];
    sh[t] = s; __syncthreads();
    for (int off = 1; off < 1024; off <<= 1) {
        int v = (t >= off) ? sh[t - off] : 0;
        __syncthreads();
        sh[t] += v;
        __syncthreads();
    }
    int run = (t > 0) ? sh[t - 1] : 0;
    for (int i = lo; i < hi; i++) { start[i] = run; cursor[i] = run; run += cnt[i]; }
    if (hi == n && lo < n) start[n] = run;
}

__global__ void k_fill(const int* __restrict__ pinned_src, const int* __restrict__ pf_src) {
    int t = blockIdx.x * blockDim.x + threadIdx.x;
    if (t < NE) {
        int s = pinned_src[t];
        int slot = atomicAdd(&g_cur_net[s], 1);
        g_csr_net[slot] = t;
    } else if (t < 2 * NE) {
        int e = t - NE;
        int s = pf_src[e];
        int slot = atomicAdd(&g_cur_han[s], 1);
        g_csr_han[slot] = e;
    }
}

// GraphConv scatter: 8 threads/edge, float4 vector REDs. 3 edge sets.
__global__ void k_gc_scatter(const float* __restrict__ node_feat, const float* __restrict__ hanna_feat,
                             const int* __restrict__ pins_src, const int* __restrict__ pins_dst,
                             const int* __restrict__ connect_src, const int* __restrict__ connect_dst,
                             const int* __restrict__ pt_src, const int* __restrict__ pt_dst) {
    int gt = blockIdx.x * blockDim.x + threadIdx.x;
    int ge = gt >> 3;
    int j = gt & 7;
    if (ge >= 3 * NE) return;
    const float* feat; const int* srcA; const int* dstA; const int* cnt; float* agg; int e;
    if (ge < NE)          { e = ge;          feat = node_feat;  srcA = pins_src;    dstA = pins_dst;    cnt = g_cnt_pins_src;    agg = g_agg_net;   }
    else if (ge < 2 * NE) { e = ge - NE;     feat = hanna_feat; srcA = connect_src; dstA = connect_dst; cnt = g_cnt_connect_src; agg = g_agg_gc_c;  }
    else                  { e = ge - 2 * NE; feat = node_feat;  srcA = pt_src;      dstA = pt_dst;      cnt = g_cnt_pt_src;      agg = g_agg_gc_pt; }
    int s = srcA[e], d = dstA[e];
    float scale = rsqrtf((float)max(cnt[s], 1));
    float4 f = ((const float4*)(feat + (size_t)s * D))[j];
    f.x *= scale; f.y *= scale; f.z *= scale; f.w *= scale;
    red_add_f4(agg + (size_t)d * D + j * 4, f);
}

// Fused NNConv: each block owns TSRC=16 consecutive source nodes.
// Phase 1 (tensor cores): G(16x544) = h(16x32) @ Wr(32x544) via tf32 mma.m16n8k8.
//   Warp p computes its 32-wide chunk (G[:, p, :]); Wr chunk p = W_topo row p
//   reshaped (32x32), chunk 16 = b_topo reshaped (32x32).
// Phase 2: stream contiguous CSR edge slice; 8 lanes/edge,
//   m_e = sum_p c_ep * G[t][p][:], scatter with float4 RED.
__global__ __launch_bounds__(544, 2) void k_nn(
        const float* __restrict__ net_feat, const float* __restrict__ hanna_feat,
        const float* __restrict__ W_topo, const float* __restrict__ b_topo,
        const float* __restrict__ pin_feat, const float* __restrict__ edge_feat,
        const int* __restrict__ pinned_src, const int* __restrict__ pinned_dst,
        const int* __restrict__ pf_src, const int* __restrict__ pf_dst) {
    __shared__ float sh_h[TSRC * D];              // 16 x 32
    __shared__ float sh_G[TSRC * GP * D];         // 16 x 17 x 32 = 34.8 KB

    int bid = blockIdx.x;
    const float* h; const float* ef; const int* srcA; const int* dstA;
    const int* start; const int* csr; float* agg; int first;
    if (bid < NB_NET_NN) {
        first = bid * TSRC;
        h = net_feat; ef = pin_feat; srcA = pinned_src; dstA = pinned_dst;
        start = g_start_net; csr = g_csr_net; agg = g_agg_cell_pd;
    } else {
        first = (bid - NB_NET_NN) * TSRC;
        h = hanna_feat; ef = edge_feat; srcA = pf_src; dstA = pf_dst;
        start = g_start_han; csr = g_csr_han; agg = g_agg_cell_pf;
    }
    int tid = threadIdx.x;

    if (tid < TSRC * D) sh_h[tid] = h[(size_t)first * D + tid];
    __syncthreads();

    // ---- phase 1: tf32 tensor-core GEMM ----
    {
        int p = tid >> 5;
        int lane = tid & 31;
        int grp = lane >> 2, tig = lane & 3;
        const float* Bp = (p < DPF) ? (W_topo + p * (D * D)) : b_topo;

        unsigned a[4][4];
#pragma unroll
        for (int ks = 0; ks < 4; ks++) {
            a[ks][0] = cvt_tf32(sh_h[grp * D + 8 * ks + tig]);
            a[ks][1] = cvt_tf32(sh_h[(grp + 8) * D + 8 * ks + tig]);
            a[ks][2] = cvt_tf32(sh_h[grp * D + 8 * ks + tig + 4]);
            a[ks][3] = cvt_tf32(sh_h[(grp + 8) * D + 8 * ks + tig + 4]);
        }
#pragma unroll
        for (int nt = 0; nt < 4; nt++) {
            float c[4] = {0.f, 0.f, 0.f, 0.f};
#pragma unroll
            for (int ks = 0; ks < 4; ks++) {
                unsigned b0 = cvt_tf32(Bp[(8 * ks + tig) * D + 8 * nt + grp]);
                unsigned b1 = cvt_tf32(Bp[(8 * ks + tig + 4) * D + 8 * nt + grp]);
                mma_tf32(c, a[ks][0], a[ks][1], a[ks][2], a[ks][3], b0, b1);
            }
            *(float2*)&sh_G[grp * (GP * D) + p * D + 8 * nt + 2 * tig] = make_float2(c[0], c[1]);
            *(float2*)&sh_G[(grp + 8) * (GP * D) + p * D + 8 * nt + 2 * tig] = make_float2(c[2], c[3]);
        }
    }
    __syncthreads();

    // ---- phase 2: edge streaming ----
    int bs = start[first];
    int nE = start[first + TSRC] - bs;
    int grp8 = tid >> 3;       // 68 groups of 8
    int j8 = tid & 7;
    int iters = (nE + 67) / 68;
    for (int it = 0; it < iters; it++) {
        int j = it * 68 + grp8;
        bool valid = j < nE;
        int eid = csr[bs + (valid ? j : 0)];
        int s = srcA[eid];
        int t = s - first;
        int d = dstA[eid];
        float2 c2 = ((const float2*)(ef + (size_t)eid * DPF))[j8];
        const float* Gt = sh_G + t * (GP * D);
        float4 a = {0.f, 0.f, 0.f, 0.f};
#pragma unroll
        for (int p = 0; p < GP; p++) {
            float cp;
            if (p < DPF) cp = __shfl_sync(0xffffffffu, (p & 1) ? c2.y : c2.x, p >> 1, 8);
            else cp = 1.f;
            float4 g4 = ((const float4*)(Gt + p * D))[j8];
            a.x = fmaf(cp, g4.x, a.x);
            a.y = fmaf(cp, g4.y, a.y);
            a.z = fmaf(cp, g4.z, a.z);
            a.w = fmaf(cp, g4.w, a.w);
        }
        if (valid) red_add_f4(agg + (size_t)d * D + j8 * 4, a);
    }
}

// merged epilogue: block ranges dispatch cell / net / gcell outputs
#define NBF_CELL ((N_CELL * D) / 256)   // 6250
#define NBF_NET  (N_NET / 8)            // 1250
#define NBF_GC   (N_GCELL / 8)          // 2500
__global__ void k_final(const float* __restrict__ net_feat,
                        const float* __restrict__ W_pins, const float* __restrict__ b_pins,
                        const float* __restrict__ W_net, const float* __restrict__ b_net,
                        const float* __restrict__ W_connect, const float* __restrict__ b_connect,
                        const float* __restrict__ W_pt, const float* __restrict__ b_pt,
                        const float* __restrict__ b_pinned, const float* __restrict__ b_pf,
                        float* __restrict__ out_cell, float* __restrict__ out_net,
                        float* __restrict__ out_gcell) {
    __shared__ float sW1[D * D], sW2[D * D];
    int b = blockIdx.x;
    if (b < NBF_CELL) {
        int idx = b * 256 + threadIdx.x;
        int c = idx >> 5, o = idx & 31;
        float d1 = (float)max(g_cnt_pinned_dst[c], 1);
        float d2 = (float)max(g_cnt_pf_dst[c], 1);
        out_cell[idx] = g_agg_cell_pd[idx] / d1 + b_pinned[o]
                      + g_agg_cell_pf[idx] / d2 + b_pf[o];
        return;
    }
    if (b < NBF_CELL + NBF_NET) {
        for (int i = threadIdx.x; i < D * D; i += 256) { sW1[i] = W_pins[i]; sW2[i] = W_net[i]; }
        __syncthreads();
        int n = (b - NBF_CELL) * 8 + (threadIdx.x >> 5);
        int o = threadIdx.x & 31;
        float acc = 0.f, acc2 = 0.f;
#pragma unroll
        for (int i = 0; i < D; i++) {
            acc  = fmaf(g_agg_net[n * D + i], sW1[i * D + o], acc);
            acc2 = fmaf(net_feat[n * D + i],  sW2[i * D + o], acc2);
        }
        float ddn = rsqrtf((float)max(g_cnt_pins_dst[n], 1));
        out_net[n * D + o] = acc * ddn + b_pins[o] + acc2 + b_net[o];
        return;
    }
    {
        for (int i = threadIdx.x; i < D * D; i += 256) { sW1[i] = W_connect[i]; sW2[i] = W_pt[i]; }
        __syncthreads();
        int g = (b - NBF_CELL - NBF_NET) * 8 + (threadIdx.x >> 5);
        int o = threadIdx.x & 31;
        float acc = 0.f, acc2 = 0.f;
#pragma unroll
        for (int i = 0; i < D; i++) {
            acc  = fmaf(g_agg_gc_c[g * D + i],  sW1[i * D + o], acc);
            acc2 = fmaf(g_agg_gc_pt[g * D + i], sW2[i * D + o], acc2);
        }
        float dc = rsqrtf((float)max(g_cnt_connect_dst[g], 1));
        float dp = rsqrtf((float)max(g_cnt_pt_dst[g], 1));
        out_gcell[g * D + o] = acc * dc + b_connect[o] + acc2 * dp + b_pt[o];
    }
}

// ---------------- launch ----------------

extern "C" void kernel_launch(void* const* d_in, const int* in_sizes, int n_in,
                              void* d_out, int out_size) {
    const float* node_feat   = (const float*)d_in[0];
    const float* net_feat    = (const float*)d_in[1];
    const float* pin_feat    = (const float*)d_in[2];
    const float* hanna_feat  = (const float*)d_in[3];
    const float* edge_feat   = (const float*)d_in[4];
    const int* pins_src      = (const int*)d_in[5];
    const int* pins_dst      = (const int*)d_in[6];
    const int* pinned_src    = (const int*)d_in[7];
    const int* pinned_dst    = (const int*)d_in[8];
    const int* connect_src   = (const int*)d_in[9];
    const int* connect_dst   = (const int*)d_in[10];
    const int* pt_src        = (const int*)d_in[11];
    const int* pt_dst        = (const int*)d_in[12];
    const int* pf_src        = (const int*)d_in[13];
    const int* pf_dst        = (const int*)d_in[14];
    const float* W_net       = (const float*)d_in[15];
    const float* b_net       = (const float*)d_in[16];
    const float* W_topo      = (const float*)d_in[17];
    const float* b_topo      = (const float*)d_in[18];
    const float* W_pins      = (const float*)d_in[19];
    const float* b_pins      = (const float*)d_in[20];
    const float* W_connect   = (const float*)d_in[21];
    const float* b_connect   = (const float*)d_in[22];
    const float* W_pt        = (const float*)d_in[23];
    const float* b_pt        = (const float*)d_in[24];
    const float* b_pinned    = (const float*)d_in[25];
    const float* b_pf        = (const float*)d_in[26];

    float* out       = (float*)d_out;
    float* out_cell  = out;
    float* out_net   = out + (size_t)N_CELL * D;
    float* out_gcell = out + (size_t)(N_CELL + N_NET) * D;

    k_zero<<<1024, 256>>>();
    k_deg<<<(NE + 255) / 256, 256>>>(pins_src, pins_dst, pinned_src, pinned_dst,
                                     connect_src, connect_dst, pt_src, pt_dst,
                                     pf_src, pf_dst);
    k_scan<<<2, 1024>>>();
    k_fill<<<(2 * NE + 255) / 256, 256>>>(pinned_src, pf_src);
    k_gc_scatter<<<(3 * NE * 8 + 255) / 256, 256>>>(node_feat, hanna_feat,
                                                    pins_src, pins_dst,
                                                    connect_src, connect_dst,
                                                    pt_src, pt_dst);
    k_nn<<<NB_NET_NN + NB_GC_NN, 544>>>(net_feat, hanna_feat, W_topo, b_topo,
                                        pin_feat, edge_feat,
                                        pinned_src, pinned_dst, pf_src, pf_dst);
    k_final<<<NBF_CELL + NBF_NET + NBF_GC, 256>>>(net_feat, W_pins, b_pins, W_net, b_net,
                                                  W_connect, b_connect, W_pt, b_pt,
                                                  b_pinned, b_pf,
                                                  out_cell, out_net, out_gcell);
}

// round 6
// speedup vs baseline: 1.0015x; 1.0015x over previous
#include <cuda_runtime.h>

#define N_CELL  50000
#define N_NET   10000
#define N_GCELL 20000
#define NE      100000
#define D       32
#define DPF     16
#define GP      17           // DPF + 1 (bias-matrix row block)
#define TSRC    16           // source nodes per fused-nnconv block
#define NB_NET_NN (N_NET / TSRC)     // 625
#define NB_GC_NN  (N_GCELL / TSRC)   // 1250

// ---------------- scratch (static device globals; no allocs) ------------
__device__ __align__(16) float g_agg_net[N_NET * D];
__device__ __align__(16) float g_agg_gc_c[N_GCELL * D];
__device__ __align__(16) float g_agg_gc_pt[N_GCELL * D];
__device__ __align__(16) float g_agg_cell_pd[N_CELL * D];
__device__ __align__(16) float g_agg_cell_pf[N_CELL * D];
__device__ __align__(16) int g_cnt_pins_src[N_CELL];
__device__ __align__(16) int g_cnt_pins_dst[N_NET];
__device__ __align__(16) int g_cnt_pinned_dst[N_CELL];
__device__ __align__(16) int g_cnt_pinned_src[N_NET];
__device__ __align__(16) int g_cnt_connect_src[N_GCELL];
__device__ __align__(16) int g_cnt_connect_dst[N_GCELL];
__device__ __align__(16) int g_cnt_pt_src[N_CELL];
__device__ __align__(16) int g_cnt_pt_dst[N_GCELL];
__device__ __align__(16) int g_cnt_pf_dst[N_CELL];
__device__ __align__(16) int g_cnt_pf_src[N_GCELL];
__device__ int g_start_net[N_NET + 1];
__device__ int g_start_han[N_GCELL + 1];
__device__ int g_cur_net[N_NET];
__device__ int g_cur_han[N_GCELL];
__device__ int g_csr_net[NE];
__device__ int g_csr_han[NE];

// vector reduction to global (sm_90+)
__device__ __forceinline__ void red_add_f4(float* p, float4 v) {
    asm volatile("red.global.add.v4.f32 [%0], {%1,%2,%3,%4};"
                 :: "l"(p), "f"(v.x), "f"(v.y), "f"(v.z), "f"(v.w) : "memory");
}

__device__ __forceinline__ unsigned cvt_tf32(float x) {
    unsigned r;
    asm("cvt.rna.tf32.f32 %0, %1;" : "=r"(r) : "f"(x));
    return r;
}

__device__ __forceinline__ void mma_tf32(float c[4],
        unsigned a0, unsigned a1, unsigned a2, unsigned a3,
        unsigned b0, unsigned b1) {
    asm("mma.sync.aligned.m16n8k8.row.col.f32.tf32.tf32.f32 "
        "{%0,%1,%2,%3}, {%4,%5,%6,%7}, {%8,%9}, {%0,%1,%2,%3};"
        : "+f"(c[0]), "+f"(c[1]), "+f"(c[2]), "+f"(c[3])
        : "r"(a0), "r"(a1), "r"(a2), "r"(a3), "r"(b0), "r"(b1));
}

// ---------------- kernels ----------------

// vectorized zero of aggs (float4) + counts (int4). All sizes /4 exact.
#define ZF4 ((N_NET*D + 2*N_GCELL*D + 2*N_CELL*D) / 4)      // 1,200,000 float4
#define ZI4 ((2*N_CELL + 2*N_NET + 4*N_GCELL + 2*N_CELL) / 4) // 60,000 int4
__global__ void k_zero() {
    int tid = blockIdx.x * blockDim.x + threadIdx.x;
    int stride = gridDim.x * blockDim.x;
    float4 z4 = {0.f, 0.f, 0.f, 0.f};
    int4 zi = {0, 0, 0, 0};
    float4* f = (float4*)g_agg_net;   // contiguity across separate symbols not guaranteed;
    // zero each array separately with grid-stride on float4 granularity
    for (int i = tid; i < N_NET * D / 4; i += stride) ((float4*)g_agg_net)[i] = z4;
    for (int i = tid; i < N_GCELL * D / 4; i += stride) { ((float4*)g_agg_gc_c)[i] = z4; ((float4*)g_agg_gc_pt)[i] = z4; }
    for (int i = tid; i < N_CELL * D / 4; i += stride) { ((float4*)g_agg_cell_pd)[i] = z4; ((float4*)g_agg_cell_pf)[i] = z4; }
    for (int i = tid; i < N_CELL / 4; i += stride) {
        ((int4*)g_cnt_pins_src)[i] = zi; ((int4*)g_cnt_pinned_dst)[i] = zi;
        ((int4*)g_cnt_pt_src)[i] = zi;   ((int4*)g_cnt_pf_dst)[i] = zi;
    }
    for (int i = tid; i < N_NET / 4; i += stride) { ((int4*)g_cnt_pins_dst)[i] = zi; ((int4*)g_cnt_pinned_src)[i] = zi; }
    for (int i = tid; i < N_GCELL / 4; i += stride) {
        ((int4*)g_cnt_connect_src)[i] = zi; ((int4*)g_cnt_connect_dst)[i] = zi;
        ((int4*)g_cnt_pt_dst)[i] = zi;      ((int4*)g_cnt_pf_src)[i] = zi;
    }
    (void)f;
}

__global__ void k_deg(const int* __restrict__ pins_src, const int* __restrict__ pins_dst,
                      const int* __restrict__ pinned_src, const int* __restrict__ pinned_dst,
                      const int* __restrict__ connect_src, const int* __restrict__ connect_dst,
                      const int* __restrict__ pt_src, const int* __restrict__ pt_dst,
                      const int* __restrict__ pf_src, const int* __restrict__ pf_dst) {
    int e = blockIdx.x * blockDim.x + threadIdx.x;
    if (e >= NE) return;
    atomicAdd(&g_cnt_pins_src[pins_src[e]], 1);
    atomicAdd(&g_cnt_pins_dst[pins_dst[e]], 1);
    atomicAdd(&g_cnt_pinned_src[pinned_src[e]], 1);
    atomicAdd(&g_cnt_pinned_dst[pinned_dst[e]], 1);
    atomicAdd(&g_cnt_connect_src[connect_src[e]], 1);
    atomicAdd(&g_cnt_connect_dst[connect_dst[e]], 1);
    atomicAdd(&g_cnt_pt_src[pt_src[e]], 1);
    atomicAdd(&g_cnt_pt_dst[pt_dst[e]], 1);
    atomicAdd(&g_cnt_pf_src[pf_src[e]], 1);
    atomicAdd(&g_cnt_pf_dst[pf_dst[e]], 1);
}

// exclusive scan of out-degree counts -> CSR row starts + fill cursors.
__global__ void k_scan() {
    const int* cnt; int* start; int* cursor; int n;
    if (blockIdx.x == 0) { cnt = g_cnt_pinned_src; start = g_start_net; cursor = g_cur_net; n = N_NET; }
    else                 { cnt = g_cnt_pf_src;     start = g_start_han; cursor = g_cur_han; n = N_GCELL; }
    int t = threadIdx.x;
    int chunk = (n + 1023) / 1024;
    int lo = t * chunk, hi = min(lo + chunk, n);
    int s = 0;
    for (int i = lo; i < hi; i++) s += cnt[i];
    __shared__ int sh[1024];
    sh[t] = s; __syncthreads();
    for (int off = 1; off < 1024; off <<= 1) {
        int v = (t >= off) ? sh[t - off] : 0;
        __syncthreads();
        sh[t] += v;
        __syncthreads();
    }
    int run = (t > 0) ? sh[t - 1] : 0;
    for (int i = lo; i < hi; i++) { start[i] = run; cursor[i] = run; run += cnt[i]; }
    if (hi == n && lo < n) start[n] = run;
}

__global__ void k_fill(const int* __restrict__ pinned_src, const int* __restrict__ pf_src) {
    int t = blockIdx.x * blockDim.x + threadIdx.x;
    if (t < NE) {
        int s = pinned_src[t];
        int slot = atomicAdd(&g_cur_net[s], 1);
        g_csr_net[slot] = t;
    } else if (t < 2 * NE) {
        int e = t - NE;
        int s = pf_src[e];
        int slot = atomicAdd(&g_cur_han[s], 1);
        g_csr_han[slot] = e;
    }
}

// GraphConv scatter: 8 threads/edge, float4 vector REDs. 3 edge sets.
__global__ void k_gc_scatter(const float* __restrict__ node_feat, const float* __restrict__ hanna_feat,
                             const int* __restrict__ pins_src, const int* __restrict__ pins_dst,
                             const int* __restrict__ connect_src, const int* __restrict__ connect_dst,
                             const int* __restrict__ pt_src, const int* __restrict__ pt_dst) {
    int gt = blockIdx.x * blockDim.x + threadIdx.x;
    int ge = gt >> 3;
    int j = gt & 7;
    if (ge >= 3 * NE) return;
    const float* feat; const int* srcA; const int* dstA; const int* cnt; float* agg; int e;
    if (ge < NE)          { e = ge;          feat = node_feat;  srcA = pins_src;    dstA = pins_dst;    cnt = g_cnt_pins_src;    agg = g_agg_net;   }
    else if (ge < 2 * NE) { e = ge - NE;     feat = hanna_feat; srcA = connect_src; dstA = connect_dst; cnt = g_cnt_connect_src; agg = g_agg_gc_c;  }
    else                  { e = ge - 2 * NE; feat = node_feat;  srcA = pt_src;      dstA = pt_dst;      cnt = g_cnt_pt_src;      agg = g_agg_gc_pt; }
    int s = srcA[e], d = dstA[e];
    float scale = rsqrtf((float)max(cnt[s], 1));
    float4 f = ((const float4*)(feat + (size_t)s * D))[j];
    f.x *= scale; f.y *= scale; f.z *= scale; f.w *= scale;
    red_add_f4(agg + (size_t)d * D + j * 4, f);
}

// Fused NNConv: each block owns TSRC=16 consecutive source nodes.
// Phase 1 (tensor cores): G(16x544) = h(16x32) @ Wr(32x544) via tf32 mma.m16n8k8.
//   Warp p computes its 32-wide chunk (G[:, p, :]); Wr chunk p = W_topo row p
//   reshaped (32x32), chunk 16 = b_topo reshaped (32x32).
// Phase 2: stream contiguous CSR edge slice; 8 lanes/edge,
//   m_e = sum_p c_ep * G[t][p][:], scatter with float4 RED.
__global__ __launch_bounds__(544, 2) void k_nn(
        const float* __restrict__ net_feat, const float* __restrict__ hanna_feat,
        const float* __restrict__ W_topo, const float* __restrict__ b_topo,
        const float* __restrict__ pin_feat, const float* __restrict__ edge_feat,
        const int* __restrict__ pinned_src, const int* __restrict__ pinned_dst,
        const int* __restrict__ pf_src, const int* __restrict__ pf_dst) {
    __shared__ float sh_h[TSRC * D];              // 16 x 32
    __shared__ float sh_G[TSRC * GP * D];         // 16 x 17 x 32 = 34.8 KB

    int bid = blockIdx.x;
    const float* h; const float* ef; const int* srcA; const int* dstA;
    const int* start; const int* csr; float* agg; int first;
    if (bid < NB_NET_NN) {
        first = bid * TSRC;
        h = net_feat; ef = pin_feat; srcA = pinned_src; dstA = pinned_dst;
        start = g_start_net; csr = g_csr_net; agg = g_agg_cell_pd;
    } else {
        first = (bid - NB_NET_NN) * TSRC;
        h = hanna_feat; ef = edge_feat; srcA = pf_src; dstA = pf_dst;
        start = g_start_han; csr = g_csr_han; agg = g_agg_cell_pf;
    }
    int tid = threadIdx.x;

    if (tid < TSRC * D) sh_h[tid] = h[(size_t)first * D + tid];
    __syncthreads();

    // ---- phase 1: tf32 tensor-core GEMM ----
    {
        int p = tid >> 5;
        int lane = tid & 31;
        int grp = lane >> 2, tig = lane & 3;
        const float* Bp = (p < DPF) ? (W_topo + p * (D * D)) : b_topo;

        unsigned a[4][4];
#pragma unroll
        for (int ks = 0; ks < 4; ks++) {
            a[ks][0] = cvt_tf32(sh_h[grp * D + 8 * ks + tig]);
            a[ks][1] = cvt_tf32(sh_h[(grp + 8) * D + 8 * ks + tig]);
            a[ks][2] = cvt_tf32(sh_h[grp * D + 8 * ks + tig + 4]);
            a[ks][3] = cvt_tf32(sh_h[(grp + 8) * D + 8 * ks + tig + 4]);
        }
#pragma unroll
        for (int nt = 0; nt < 4; nt++) {
            float c[4] = {0.f, 0.f, 0.f, 0.f};
#pragma unroll
            for (int ks = 0; ks < 4; ks++) {
                unsigned b0 = cvt_tf32(Bp[(8 * ks + tig) * D + 8 * nt + grp]);
                unsigned b1 = cvt_tf32(Bp[(8 * ks + tig + 4) * D + 8 * nt + grp]);
                mma_tf32(c, a[ks][0], a[ks][1], a[ks][2], a[ks][3], b0, b1);
            }
            *(float2*)&sh_G[grp * (GP * D) + p * D + 8 * nt + 2 * tig] = make_float2(c[0], c[1]);
            *(float2*)&sh_G[(grp + 8) * (GP * D) + p * D + 8 * nt + 2 * tig] = make_float2(c[2], c[3]);
        }
    }
    __syncthreads();

    // ---- phase 2: edge streaming ----
    int bs = start[first];
    int nE = start[first + TSRC] - bs;
    int grp8 = tid >> 3;       // 68 groups of 8
    int j8 = tid & 7;
    int iters = (nE + 67) / 68;
    for (int it = 0; it < iters; it++) {
        int j = it * 68 + grp8;
        bool valid = j < nE;
        int eid = csr[bs + (valid ? j : 0)];
        int s = srcA[eid];
        int t = s - first;
        int d = dstA[eid];
        float2 c2 = ((const float2*)(ef + (size_t)eid * DPF))[j8];
        const float* Gt = sh_G + t * (GP * D);
        float4 a = {0.f, 0.f, 0.f, 0.f};
#pragma unroll
        for (int p = 0; p < GP; p++) {
            float cp;
            if (p < DPF) cp = __shfl_sync(0xffffffffu, (p & 1) ? c2.y : c2.x, p >> 1, 8);
            else cp = 1.f;
            float4 g4 = ((const float4*)(Gt + p * D))[j8];
            a.x = fmaf(cp, g4.x, a.x);
            a.y = fmaf(cp, g4.y, a.y);
            a.z = fmaf(cp, g4.z, a.z);
            a.w = fmaf(cp, g4.w, a.w);
        }
        if (valid) red_add_f4(agg + (size_t)d * D + j8 * 4, a);
    }
}

// merged epilogue: block ranges dispatch cell / net / gcell outputs
#define NBF_CELL ((N_CELL * D) / 256)   // 6250
#define NBF_NET  (N_NET / 8)            // 1250
#define NBF_GC   (N_GCELL / 8)          // 2500
__global__ void k_final(const float* __restrict__ net_feat,
                        const float* __restrict__ W_pins, const float* __restrict__ b_pins,
                        const float* __restrict__ W_net, const float* __restrict__ b_net,
                        const float* __restrict__ W_connect, const float* __restrict__ b_connect,
                        const float* __restrict__ W_pt, const float* __restrict__ b_pt,
                        const float* __restrict__ b_pinned, const float* __restrict__ b_pf,
                        float* __restrict__ out_cell, float* __restrict__ out_net,
                        float* __restrict__ out_gcell) {
    __shared__ float sW1[D * D], sW2[D * D];
    int b = blockIdx.x;
    if (b < NBF_CELL) {
        int idx = b * 256 + threadIdx.x;
        int c = idx >> 5, o = idx & 31;
        float d1 = (float)max(g_cnt_pinned_dst[c], 1);
        float d2 = (float)max(g_cnt_pf_dst[c], 1);
        out_cell[idx] = g_agg_cell_pd[idx] / d1 + b_pinned[o]
                      + g_agg_cell_pf[idx] / d2 + b_pf[o];
        return;
    }
    if (b < NBF_CELL + NBF_NET) {
        for (int i = threadIdx.x; i < D * D; i += 256) { sW1[i] = W_pins[i]; sW2[i] = W_net[i]; }
        __syncthreads();
        int n = (b - NBF_CELL) * 8 + (threadIdx.x >> 5);
        int o = threadIdx.x & 31;
        float acc = 0.f, acc2 = 0.f;
#pragma unroll
        for (int i = 0; i < D; i++) {
            acc  = fmaf(g_agg_net[n * D + i], sW1[i * D + o], acc);
            acc2 = fmaf(net_feat[n * D + i],  sW2[i * D + o], acc2);
        }
        float ddn = rsqrtf((float)max(g_cnt_pins_dst[n], 1));
        out_net[n * D + o] = acc * ddn + b_pins[o] + acc2 + b_net[o];
        return;
    }
    {
        for (int i = threadIdx.x; i < D * D; i += 256) { sW1[i] = W_connect[i]; sW2[i] = W_pt[i]; }
        __syncthreads();
        int g = (b - NBF_CELL - NBF_NET) * 8 + (threadIdx.x >> 5);
        int o = threadIdx.x & 31;
        float acc = 0.f, acc2 = 0.f;
#pragma unroll
        for (int i = 0; i < D; i++) {
            acc  = fmaf(g_agg_gc_c[g * D + i],  sW1[i * D + o], acc);
            acc2 = fmaf(g_agg_gc_pt[g * D + i], sW2[i * D + o], acc2);
        }
        float dc = rsqrtf((float)max(g_cnt_connect_dst[g], 1));
        float dp = rsqrtf((float)max(g_cnt_pt_dst[g], 1));
        out_gcell[g * D + o] = acc * dc + b_connect[o] + acc2 * dp + b_pt[o];
    }
}

// ---------------- launch ----------------

extern "C" void kernel_launch(void* const* d_in, const int* in_sizes, int n_in,
                              void* d_out, int out_size) {
    const float* node_feat   = (const float*)d_in[0];
    const float* net_feat    = (const float*)d_in[1];
    const float* pin_feat    = (const float*)d_in[2];
    const float* hanna_feat  = (const float*)d_in[3];
    const float* edge_feat   = (const float*)d_in[4];
    const int* pins_src      = (const int*)d_in[5];
    const int* pins_dst      = (const int*)d_in[6];
    const int* pinned_src    = (const int*)d_in[7];
    const int* pinned_dst    = (const int*)d_in[8];
    const int* connect_src   = (const int*)d_in[9];
    const int* connect_dst   = (const int*)d_in[10];
    const int* pt_src        = (const int*)d_in[11];
    const int* pt_dst        = (const int*)d_in[12];
    const int* pf_src        = (const int*)d_in[13];
    const int* pf_dst        = (const int*)d_in[14];
    const float* W_net       = (const float*)d_in[15];
    const float* b_net       = (const float*)d_in[16];
    const float* W_topo      = (const float*)d_in[17];
    const float* b_topo      = (const float*)d_in[18];
    const float* W_pins      = (const float*)d_in[19];
    const float* b_pins      = (const float*)d_in[20];
    const float* W_connect   = (const float*)d_in[21];
    const float* b_connect   = (const float*)d_in[22];
    const float* W_pt        = (const float*)d_in[23];
    const float* b_pt        = (const float*)d_in[24];
    const float* b_pinned    = (const float*)d_in[25];
    const float* b_pf        = (const float*)d_in[26];

    float* out       = (float*)d_out;
    float* out_cell  = out;
    float* out_net   = out + (size_t)N_CELL * D;
    float* out_gcell = out + (size_t)(N_CELL + N_NET) * D;

    k_zero<<<1024, 256>>>();
    k_deg<<<(NE + 255) / 256, 256>>>(pins_src, pins_dst, pinned_src, pinned_dst,
                                     connect_src, connect_dst, pt_src, pt_dst,
                                     pf_src, pf_dst);
    k_scan<<<2, 1024>>>();
    k_fill<<<(2 * NE + 255) / 256, 256>>>(pinned_src, pf_src);
    k_gc_scatter<<<(3 * NE * 8 + 255) / 256, 256>>>(node_feat, hanna_feat,
                                                    pins_src, pins_dst,
                                                    connect_src, connect_dst,
                                                    pt_src, pt_dst);
    k_nn<<<NB_NET_NN + NB_GC_NN, 544>>>(net_feat, hanna_feat, W_topo, b_topo,
                                        pin_feat, edge_feat,
                                        pinned_src, pinned_dst, pf_src, pf_dst);
    k_final<<<NBF_CELL + NBF_NET + NBF_GC, 256>>>(net_feat, W_pins, b_pins, W_net, b_net,
                                                  W_connect, b_connect, W_pt, b_pt,
                                                  b_pinned, b_pf,
                                                  out_cell, out_net, out_gcell);
}

// round 7
// speedup vs baseline: 1.0591x; 1.0575x over previous
#include <cuda_runtime.h>

#define N_CELL  50000
#define N_NET   10000
#define N_GCELL 20000
#define NE      100000
#define D       32
#define DPF     16
#define GP      17           // DPF + 1 (bias row)
#define TSRC    16           // source nodes per fused-nnconv block
#define NB_NET_NN (N_NET / TSRC)     // 625
#define NB_GC_NN  (N_GCELL / TSRC)   // 1250

// ---------------- scratch (static device globals; no allocs) ------------
__device__ __align__(16) float g_agg_net[N_NET * D];
__device__ __align__(16) float g_agg_gc_c[N_GCELL * D];
__device__ __align__(16) float g_agg_gc_pt[N_GCELL * D];
__device__ __align__(16) float g_agg_cell_pd[N_CELL * D];
__device__ __align__(16) float g_agg_cell_pf[N_CELL * D];
__device__ __align__(16) int g_cnt_pins_src[N_CELL];
__device__ __align__(16) int g_cnt_pins_dst[N_NET];
__device__ __align__(16) int g_cnt_pinned_dst[N_CELL];
__device__ __align__(16) int g_cnt_pinned_src[N_NET];
__device__ __align__(16) int g_cnt_connect_src[N_GCELL];
__device__ __align__(16) int g_cnt_connect_dst[N_GCELL];
__device__ __align__(16) int g_cnt_pt_src[N_CELL];
__device__ __align__(16) int g_cnt_pt_dst[N_GCELL];
__device__ __align__(16) int g_cnt_pf_dst[N_CELL];
__device__ __align__(16) int g_cnt_pf_src[N_GCELL];
__device__ int g_start_net[N_NET + 1];
__device__ int g_start_han[N_GCELL + 1];
__device__ int g_cur_net[N_NET];
__device__ int g_cur_han[N_GCELL];
__device__ int g_csr_net[NE];
__device__ int g_csr_han[NE];

// vector reduction to global (sm_90+)
__device__ __forceinline__ void red_add_f4(float* p, float4 v) {
    asm volatile("red.global.add.v4.f32 [%0], {%1,%2,%3,%4};"
                 :: "l"(p), "f"(v.x), "f"(v.y), "f"(v.z), "f"(v.w) : "memory");
}

// ---------------- kernels ----------------

__global__ void k_zero() {
    int tid = blockIdx.x * blockDim.x + threadIdx.x;
    int stride = gridDim.x * blockDim.x;
    float4 z4 = {0.f, 0.f, 0.f, 0.f};
    int4 zi = {0, 0, 0, 0};
    for (int i = tid; i < N_NET * D / 4; i += stride) ((float4*)g_agg_net)[i] = z4;
    for (int i = tid; i < N_GCELL * D / 4; i += stride) { ((float4*)g_agg_gc_c)[i] = z4; ((float4*)g_agg_gc_pt)[i] = z4; }
    for (int i = tid; i < N_CELL * D / 4; i += stride) { ((float4*)g_agg_cell_pd)[i] = z4; ((float4*)g_agg_cell_pf)[i] = z4; }
    for (int i = tid; i < N_CELL / 4; i += stride) {
        ((int4*)g_cnt_pins_src)[i] = zi; ((int4*)g_cnt_pinned_dst)[i] = zi;
        ((int4*)g_cnt_pt_src)[i] = zi;   ((int4*)g_cnt_pf_dst)[i] = zi;
    }
    for (int i = tid; i < N_NET / 4; i += stride) { ((int4*)g_cnt_pins_dst)[i] = zi; ((int4*)g_cnt_pinned_src)[i] = zi; }
    for (int i = tid; i < N_GCELL / 4; i += stride) {
        ((int4*)g_cnt_connect_src)[i] = zi; ((int4*)g_cnt_connect_dst)[i] = zi;
        ((int4*)g_cnt_pt_dst)[i] = zi;      ((int4*)g_cnt_pf_src)[i] = zi;
    }
}

__global__ void k_deg(const int* __restrict__ pins_src, const int* __restrict__ pins_dst,
                      const int* __restrict__ pinned_src, const int* __restrict__ pinned_dst,
                      const int* __restrict__ connect_src, const int* __restrict__ connect_dst,
                      const int* __restrict__ pt_src, const int* __restrict__ pt_dst,
                      const int* __restrict__ pf_src, const int* __restrict__ pf_dst) {
    int e = blockIdx.x * blockDim.x + threadIdx.x;
    if (e >= NE) return;
    atomicAdd(&g_cnt_pins_src[pins_src[e]], 1);
    atomicAdd(&g_cnt_pins_dst[pins_dst[e]], 1);
    atomicAdd(&g_cnt_pinned_src[pinned_src[e]], 1);
    atomicAdd(&g_cnt_pinned_dst[pinned_dst[e]], 1);
    atomicAdd(&g_cnt_connect_src[connect_src[e]], 1);
    atomicAdd(&g_cnt_connect_dst[connect_dst[e]], 1);
    atomicAdd(&g_cnt_pt_src[pt_src[e]], 1);
    atomicAdd(&g_cnt_pt_dst[pt_dst[e]], 1);
    atomicAdd(&g_cnt_pf_src[pf_src[e]], 1);
    atomicAdd(&g_cnt_pf_dst[pf_dst[e]], 1);
}

// exclusive scan of out-degree counts -> CSR row starts + fill cursors.
__global__ void k_scan() {
    const int* cnt; int* start; int* cursor; int n;
    if (blockIdx.x == 0) { cnt = g_cnt_pinned_src; start = g_start_net; cursor = g_cur_net; n = N_NET; }
    else                 { cnt = g_cnt_pf_src;     start = g_start_han; cursor = g_cur_han; n = N_GCELL; }
    int t = threadIdx.x;
    int chunk = (n + 1023) / 1024;
    int lo = t * chunk, hi = min(lo + chunk, n);
    int s = 0;
    for (int i = lo; i < hi; i++) s += cnt[i];
    __shared__ int sh[1024];
    sh[t] = s; __syncthreads();
    for (int off = 1; off < 1024; off <<= 1) {
        int v = (t >= off) ? sh[t - off] : 0;
        __syncthreads();
        sh[t] += v;
        __syncthreads();
    }
    int run = (t > 0) ? sh[t - 1] : 0;
    for (int i = lo; i < hi; i++) { start[i] = run; cursor[i] = run; run += cnt[i]; }
    if (hi == n && lo < n) start[n] = run;
}

__global__ void k_fill(const int* __restrict__ pinned_src, const int* __restrict__ pf_src) {
    int t = blockIdx.x * blockDim.x + threadIdx.x;
    if (t < NE) {
        int s = pinned_src[t];
        int slot = atomicAdd(&g_cur_net[s], 1);
        g_csr_net[slot] = t;
    } else if (t < 2 * NE) {
        int e = t - NE;
        int s = pf_src[e];
        int slot = atomicAdd(&g_cur_han[s], 1);
        g_csr_han[slot] = e;
    }
}

// GraphConv scatter: 8 threads/edge, float4 vector REDs. 3 edge sets.
__global__ void k_gc_scatter(const float* __restrict__ node_feat, const float* __restrict__ hanna_feat,
                             const int* __restrict__ pins_src, const int* __restrict__ pins_dst,
                             const int* __restrict__ connect_src, const int* __restrict__ connect_dst,
                             const int* __restrict__ pt_src, const int* __restrict__ pt_dst) {
    int gt = blockIdx.x * blockDim.x + threadIdx.x;
    int ge = gt >> 3;
    int j = gt & 7;
    if (ge >= 3 * NE) return;
    const float* feat; const int* srcA; const int* dstA; const int* cnt; float* agg; int e;
    if (ge < NE)          { e = ge;          feat = node_feat;  srcA = pins_src;    dstA = pins_dst;    cnt = g_cnt_pins_src;    agg = g_agg_net;   }
    else if (ge < 2 * NE) { e = ge - NE;     feat = hanna_feat; srcA = connect_src; dstA = connect_dst; cnt = g_cnt_connect_src; agg = g_agg_gc_c;  }
    else                  { e = ge - 2 * NE; feat = node_feat;  srcA = pt_src;      dstA = pt_dst;      cnt = g_cnt_pt_src;      agg = g_agg_gc_pt; }
    int s = srcA[e], d = dstA[e];
    float scale = rsqrtf((float)max(cnt[s], 1));
    float4 f = ((const float4*)(feat + (size_t)s * D))[j];
    f.x *= scale; f.y *= scale; f.z *= scale; f.w *= scale;
    red_add_f4(agg + (size_t)d * D + j * 4, f);
}

// Fused NNConv: each block owns TSRC=16 consecutive source nodes.
// Phase 1 (FFMA, register-tiled): G[t][p][o] = sum_i h[t][i]*Wrow_p[i*32+o] in shared.
// Phase 2: stream contiguous CSR edge slice; 8 lanes/edge, float4 RED scatter.
__global__ __launch_bounds__(544, 2) void k_nn(
        const float* __restrict__ net_feat, const float* __restrict__ hanna_feat,
        const float* __restrict__ W_topo, const float* __restrict__ b_topo,
        const float* __restrict__ pin_feat, const float* __restrict__ edge_feat,
        const int* __restrict__ pinned_src, const int* __restrict__ pinned_dst,
        const int* __restrict__ pf_src, const int* __restrict__ pf_dst) {
    __shared__ float4 sh_h4[TSRC * 8];            // 16 rows x 32 feats
    __shared__ float sh_G[TSRC * GP * D];         // 16 x 17 x 32 = 34.8 KB

    int bid = blockIdx.x;
    const float* h; const float* ef; const int* srcA; const int* dstA;
    const int* start; const int* csr; float* agg; int first;
    if (bid < NB_NET_NN) {
        first = bid * TSRC;
        h = net_feat; ef = pin_feat; srcA = pinned_src; dstA = pinned_dst;
        start = g_start_net; csr = g_csr_net; agg = g_agg_cell_pd;
    } else {
        first = (bid - NB_NET_NN) * TSRC;
        h = hanna_feat; ef = edge_feat; srcA = pf_src; dstA = pf_dst;
        start = g_start_han; csr = g_csr_han; agg = g_agg_cell_pf;
    }
    int tid = threadIdx.x;

    if (tid < TSRC * D) ((float*)sh_h4)[tid] = h[(size_t)first * D + tid];
    __syncthreads();

    // ---- phase 1: G compute (thread = (p, o), 16 accumulators) ----
    {
        int p = tid >> 5, o = tid & 31;
        const float* w = ((p < DPF) ? (W_topo + p * (D * D)) : b_topo) + o;
        float acc[TSRC];
#pragma unroll
        for (int t = 0; t < TSRC; t++) acc[t] = 0.f;
#pragma unroll
        for (int i4 = 0; i4 < 8; i4++) {
            float w0 = w[(i4 * 4 + 0) * D];
            float w1 = w[(i4 * 4 + 1) * D];
            float w2 = w[(i4 * 4 + 2) * D];
            float w3 = w[(i4 * 4 + 3) * D];
#pragma unroll
            for (int t = 0; t < TSRC; t++) {
                float4 h4 = sh_h4[t * 8 + i4];
                acc[t] = fmaf(h4.x, w0, fmaf(h4.y, w1, fmaf(h4.z, w2, fmaf(h4.w, w3, acc[t]))));
            }
        }
#pragma unroll
        for (int t = 0; t < TSRC; t++) sh_G[t * (GP * D) + p * D + o] = acc[t];
    }
    __syncthreads();

    // ---- phase 2: edge streaming ----
    int bs = start[first];
    int nE = start[first + TSRC] - bs;
    int grp = tid >> 3;        // 68 groups of 8
    int j8 = tid & 7;
    int iters = (nE + 67) / 68;
    for (int it = 0; it < iters; it++) {
        int j = it * 68 + grp;
        bool valid = j < nE;
        int eid = csr[bs + (valid ? j : 0)];
        int s = srcA[eid];
        int t = s - first;
        int d = dstA[eid];
        float2 c2 = ((const float2*)(ef + (size_t)eid * DPF))[j8];
        const float* Gt = sh_G + t * (GP * D);
        float4 a = {0.f, 0.f, 0.f, 0.f};
#pragma unroll
        for (int p = 0; p < GP; p++) {
            float cp;
            if (p < DPF) cp = __shfl_sync(0xffffffffu, (p & 1) ? c2.y : c2.x, p >> 1, 8);
            else cp = 1.f;
            float4 g4 = ((const float4*)(Gt + p * D))[j8];
            a.x = fmaf(cp, g4.x, a.x);
            a.y = fmaf(cp, g4.y, a.y);
            a.z = fmaf(cp, g4.z, a.z);
            a.w = fmaf(cp, g4.w, a.w);
        }
        if (valid) red_add_f4(agg + (size_t)d * D + j8 * 4, a);
    }
}

// merged epilogue: block ranges dispatch cell / net / gcell outputs
#define NBF_CELL ((N_CELL * D) / 256)   // 6250
#define NBF_NET  (N_NET / 8)            // 1250
#define NBF_GC   (N_GCELL / 8)          // 2500
__global__ void k_final(const float* __restrict__ net_feat,
                        const float* __restrict__ W_pins, const float* __restrict__ b_pins,
                        const float* __restrict__ W_net, const float* __restrict__ b_net,
                        const float* __restrict__ W_connect, const float* __restrict__ b_connect,
                        const float* __restrict__ W_pt, const float* __restrict__ b_pt,
                        const float* __restrict__ b_pinned, const float* __restrict__ b_pf,
                        float* __restrict__ out_cell, float* __restrict__ out_net,
                        float* __restrict__ out_gcell) {
    __shared__ float sW1[D * D], sW2[D * D];
    int b = blockIdx.x;
    if (b < NBF_CELL) {
        int idx = b * 256 + threadIdx.x;
        int c = idx >> 5, o = idx & 31;
        float d1 = (float)max(g_cnt_pinned_dst[c], 1);
        float d2 = (float)max(g_cnt_pf_dst[c], 1);
        out_cell[idx] = g_agg_cell_pd[idx] / d1 + b_pinned[o]
                      + g_agg_cell_pf[idx] / d2 + b_pf[o];
        return;
    }
    if (b < NBF_CELL + NBF_NET) {
        for (int i = threadIdx.x; i < D * D; i += 256) { sW1[i] = W_pins[i]; sW2[i] = W_net[i]; }
        __syncthreads();
        int n = (b - NBF_CELL) * 8 + (threadIdx.x >> 5);
        int o = threadIdx.x & 31;
        float acc = 0.f, acc2 = 0.f;
#pragma unroll
        for (int i = 0; i < D; i++) {
            acc  = fmaf(g_agg_net[n * D + i], sW1[i * D + o], acc);
            acc2 = fmaf(net_feat[n * D + i],  sW2[i * D + o], acc2);
        }
        float ddn = rsqrtf((float)max(g_cnt_pins_dst[n], 1));
        out_net[n * D + o] = acc * ddn + b_pins[o] + acc2 + b_net[o];
        return;
    }
    {
        for (int i = threadIdx.x; i < D * D; i += 256) { sW1[i] = W_connect[i]; sW2[i] = W_pt[i]; }
        __syncthreads();
        int g = (b - NBF_CELL - NBF_NET) * 8 + (threadIdx.x >> 5);
        int o = threadIdx.x & 31;
        float acc = 0.f, acc2 = 0.f;
#pragma unroll
        for (int i = 0; i < D; i++) {
            acc  = fmaf(g_agg_gc_c[g * D + i],  sW1[i * D + o], acc);
            acc2 = fmaf(g_agg_gc_pt[g * D + i], sW2[i * D + o], acc2);
        }
        float dc = rsqrtf((float)max(g_cnt_connect_dst[g], 1));
        float dp = rsqrtf((float)max(g_cnt_pt_dst[g], 1));
        out_gcell[g * D + o] = acc * dc + b_connect[o] + acc2 * dp + b_pt[o];
    }
}

// ---------------- launch ----------------

extern "C" void kernel_launch(void* const* d_in, const int* in_sizes, int n_in,
                              void* d_out, int out_size) {
    const float* node_feat   = (const float*)d_in[0];
    const float* net_feat    = (const float*)d_in[1];
    const float* pin_feat    = (const float*)d_in[2];
    const float* hanna_feat  = (const float*)d_in[3];
    const float* edge_feat   = (const float*)d_in[4];
    const int* pins_src      = (const int*)d_in[5];
    const int* pins_dst      = (const int*)d_in[6];
    const int* pinned_src    = (const int*)d_in[7];
    const int* pinned_dst    = (const int*)d_in[8];
    const int* connect_src   = (const int*)d_in[9];
    const int* connect_dst   = (const int*)d_in[10];
    const int* pt_src        = (const int*)d_in[11];
    const int* pt_dst        = (const int*)d_in[12];
    const int* pf_src        = (const int*)d_in[13];
    const int* pf_dst        = (const int*)d_in[14];
    const float* W_net       = (const float*)d_in[15];
    const float* b_net       = (const float*)d_in[16];
    const float* W_topo      = (const float*)d_in[17];
    const float* b_topo      = (const float*)d_in[18];
    const float* W_pins      = (const float*)d_in[19];
    const float* b_pins      = (const float*)d_in[20];
    const float* W_connect   = (const float*)d_in[21];
    const float* b_connect   = (const float*)d_in[22];
    const float* W_pt        = (const float*)d_in[23];
    const float* b_pt        = (const float*)d_in[24];
    const float* b_pinned    = (const float*)d_in[25];
    const float* b_pf        = (const float*)d_in[26];

    float* out       = (float*)d_out;
    float* out_cell  = out;
    float* out_net   = out + (size_t)N_CELL * D;
    float* out_gcell = out + (size_t)(N_CELL + N_NET) * D;

    // side stream + events for fork/join inside graph capture (created once; never freed)
    static cudaStream_t s1 = nullptr;
    static cudaEvent_t evDeg = nullptr, evNN = nullptr;
    if (s1 == nullptr) {
        cudaStreamCreateWithFlags(&s1, cudaStreamNonBlocking);
        cudaEventCreateWithFlags(&evDeg, cudaEventDisableTiming);
        cudaEventCreateWithFlags(&evNN, cudaEventDisableTiming);
    }

    // main (capture) stream: zero -> deg
    k_zero<<<1024, 256>>>();
    k_deg<<<(NE + 255) / 256, 256>>>(pins_src, pins_dst, pinned_src, pinned_dst,
                                     connect_src, connect_dst, pt_src, pt_dst,
                                     pf_src, pf_dst);
    cudaEventRecord(evDeg, 0);

    // side stream: scan -> fill -> nn (independent of gc_scatter)
    cudaStreamWaitEvent(s1, evDeg, 0);
    k_scan<<<2, 1024, 0, s1>>>();
    k_fill<<<(2 * NE + 255) / 256, 256, 0, s1>>>(pinned_src, pf_src);
    k_nn<<<NB_NET_NN + NB_GC_NN, 544, 0, s1>>>(net_feat, hanna_feat, W_topo, b_topo,
                                               pin_feat, edge_feat,
                                               pinned_src, pinned_dst, pf_src, pf_dst);
    cudaEventRecord(evNN, s1);

    // main stream (concurrent with side chain): graphconv scatters
    k_gc_scatter<<<(3 * NE * 8 + 255) / 256, 256>>>(node_feat, hanna_feat,
                                                    pins_src, pins_dst,
                                                    connect_src, connect_dst,
                                                    pt_src, pt_dst);

    // join and finish
    cudaStreamWaitEvent(0, evNN, 0);
    k_final<<<NBF_CELL + NBF_NET + NBF_GC, 256>>>(net_feat, W_pins, b_pins, W_net, b_net,
                                                  W_connect, b_connect, W_pt, b_pt,
                                                  b_pinned, b_pf,
                                                  out_cell, out_net, out_gcell);
}

// round 8
// speedup vs baseline: 1.2022x; 1.1350x over previous
#include <cuda_runtime.h>

#define N_CELL  50000
#define N_NET   10000
#define N_GCELL 20000
#define NE      100000
#define D       32
#define DPF     16
#define GP      17           // DPF + 1 (bias row)
#define TSRC    16           // source nodes per fused-nnconv block
#define NB_NET_NN (N_NET / TSRC)     // 625
#define NB_GC_NN  (N_GCELL / TSRC)   // 1250
#define CAPN    512          // bin capacity, net side (mean 160, Poisson)
#define CAPH    256          // bin capacity, gcell side (mean 80)

// ---------------- scratch (static device globals; no allocs) ------------
__device__ __align__(16) float g_agg_net[N_NET * D];
__device__ __align__(16) float g_agg_gc_c[N_GCELL * D];
__device__ __align__(16) float g_agg_gc_pt[N_GCELL * D];
__device__ __align__(16) float g_agg_cell_pd[N_CELL * D];
__device__ __align__(16) float g_agg_cell_pf[N_CELL * D];
__device__ __align__(16) int g_cnt_pins_src[N_CELL];
__device__ __align__(16) int g_cnt_pins_dst[N_NET];
__device__ __align__(16) int g_cnt_pinned_dst[N_CELL];
__device__ __align__(16) int g_cnt_connect_src[N_GCELL];
__device__ __align__(16) int g_cnt_connect_dst[N_GCELL];
__device__ __align__(16) int g_cnt_pt_src[N_CELL];
__device__ __align__(16) int g_cnt_pt_dst[N_GCELL];
__device__ __align__(16) int g_cnt_pf_dst[N_CELL];
__device__ __align__(16) int g_bincnt_net[NB_NET_NN];     // 625
__device__ __align__(16) int g_bincnt_han[NB_GC_NN];      // 1250 (pad not needed; /4 not exact for 625 -> zero scalar)
__device__ int g_bin_net[NB_NET_NN * CAPN];
__device__ int g_bin_han[NB_GC_NN * CAPH];

// vector reduction to global (sm_90+)
__device__ __forceinline__ void red_add_f4(float* p, float4 v) {
    asm volatile("red.global.add.v4.f32 [%0], {%1,%2,%3,%4};"
                 :: "l"(p), "f"(v.x), "f"(v.y), "f"(v.z), "f"(v.w) : "memory");
}

// ---------------- kernels ----------------

__global__ void k_zero() {
    int tid = blockIdx.x * blockDim.x + threadIdx.x;
    int stride = gridDim.x * blockDim.x;
    float4 z4 = {0.f, 0.f, 0.f, 0.f};
    int4 zi = {0, 0, 0, 0};
    for (int i = tid; i < N_NET * D / 4; i += stride) ((float4*)g_agg_net)[i] = z4;
    for (int i = tid; i < N_GCELL * D / 4; i += stride) { ((float4*)g_agg_gc_c)[i] = z4; ((float4*)g_agg_gc_pt)[i] = z4; }
    for (int i = tid; i < N_CELL * D / 4; i += stride) { ((float4*)g_agg_cell_pd)[i] = z4; ((float4*)g_agg_cell_pf)[i] = z4; }
    for (int i = tid; i < N_CELL / 4; i += stride) {
        ((int4*)g_cnt_pins_src)[i] = zi; ((int4*)g_cnt_pinned_dst)[i] = zi;
        ((int4*)g_cnt_pt_src)[i] = zi;   ((int4*)g_cnt_pf_dst)[i] = zi;
    }
    for (int i = tid; i < N_NET / 4; i += stride) ((int4*)g_cnt_pins_dst)[i] = zi;
    for (int i = tid; i < N_GCELL / 4; i += stride) {
        ((int4*)g_cnt_connect_src)[i] = zi; ((int4*)g_cnt_connect_dst)[i] = zi;
        ((int4*)g_cnt_pt_dst)[i] = zi;
    }
    for (int i = tid; i < NB_NET_NN; i += stride) g_bincnt_net[i] = 0;
    for (int i = tid; i < NB_GC_NN; i += stride) g_bincnt_han[i] = 0;
}

// source degrees only (gates gc_scatter)
__global__ void k_deg_src(const int* __restrict__ pins_src,
                          const int* __restrict__ connect_src,
                          const int* __restrict__ pt_src) {
    int e = blockIdx.x * blockDim.x + threadIdx.x;
    if (e >= NE) return;
    atomicAdd(&g_cnt_pins_src[pins_src[e]], 1);
    atomicAdd(&g_cnt_connect_src[connect_src[e]], 1);
    atomicAdd(&g_cnt_pt_src[pt_src[e]], 1);
}

// destination degrees only (gates k_final)
__global__ void k_deg_dst(const int* __restrict__ pins_dst, const int* __restrict__ pinned_dst,
                          const int* __restrict__ connect_dst, const int* __restrict__ pt_dst,
                          const int* __restrict__ pf_dst) {
    int e = blockIdx.x * blockDim.x + threadIdx.x;
    if (e >= NE) return;
    atomicAdd(&g_cnt_pins_dst[pins_dst[e]], 1);
    atomicAdd(&g_cnt_pinned_dst[pinned_dst[e]], 1);
    atomicAdd(&g_cnt_connect_dst[connect_dst[e]], 1);
    atomicAdd(&g_cnt_pt_dst[pt_dst[e]], 1);
    atomicAdd(&g_cnt_pf_dst[pf_dst[e]], 1);
}

// ordering-free bin append: bin = src >> 4. No scan needed.
__global__ void k_fill_bins(const int* __restrict__ pinned_src, const int* __restrict__ pf_src) {
    int e = blockIdx.x * blockDim.x + threadIdx.x;
    if (e >= NE) return;
    int b1 = pinned_src[e] >> 4;
    int s1 = atomicAdd(&g_bincnt_net[b1], 1);
    g_bin_net[b1 * CAPN + s1] = e;
    int b2 = pf_src[e] >> 4;
    int s2 = atomicAdd(&g_bincnt_han[b2], 1);
    g_bin_han[b2 * CAPH + s2] = e;
}

// GraphConv scatter: 8 threads/edge, float4 vector REDs. 3 edge sets.
__global__ void k_gc_scatter(const float* __restrict__ node_feat, const float* __restrict__ hanna_feat,
                             const int* __restrict__ pins_src, const int* __restrict__ pins_dst,
                             const int* __restrict__ connect_src, const int* __restrict__ connect_dst,
                             const int* __restrict__ pt_src, const int* __restrict__ pt_dst) {
    int gt = blockIdx.x * blockDim.x + threadIdx.x;
    int ge = gt >> 3;
    int j = gt & 7;
    if (ge >= 3 * NE) return;
    const float* feat; const int* srcA; const int* dstA; const int* cnt; float* agg; int e;
    if (ge < NE)          { e = ge;          feat = node_feat;  srcA = pins_src;    dstA = pins_dst;    cnt = g_cnt_pins_src;    agg = g_agg_net;   }
    else if (ge < 2 * NE) { e = ge - NE;     feat = hanna_feat; srcA = connect_src; dstA = connect_dst; cnt = g_cnt_connect_src; agg = g_agg_gc_c;  }
    else                  { e = ge - 2 * NE; feat = node_feat;  srcA = pt_src;      dstA = pt_dst;      cnt = g_cnt_pt_src;      agg = g_agg_gc_pt; }
    int s = srcA[e], d = dstA[e];
    float scale = rsqrtf((float)max(cnt[s], 1));
    float4 f = ((const float4*)(feat + (size_t)s * D))[j];
    f.x *= scale; f.y *= scale; f.z *= scale; f.w *= scale;
    red_add_f4(agg + (size_t)d * D + j * 4, f);
}

// Fused NNConv: block owns TSRC=16 consecutive source nodes (== one bin).
// Phase 1 (FFMA, register-tiled): G[t][p][o] = sum_i h[t][i]*Wrow_p[i*32+o] in shared.
// Phase 2: stream the bin's edges; 8 lanes/edge, float4 RED scatter.
__global__ __launch_bounds__(544, 2) void k_nn(
        const float* __restrict__ net_feat, const float* __restrict__ hanna_feat,
        const float* __restrict__ W_topo, const float* __restrict__ b_topo,
        const float* __restrict__ pin_feat, const float* __restrict__ edge_feat,
        const int* __restrict__ pinned_src, const int* __restrict__ pinned_dst,
        const int* __restrict__ pf_src, const int* __restrict__ pf_dst) {
    __shared__ float4 sh_h4[TSRC * 8];            // 16 rows x 32 feats
    __shared__ float sh_G[TSRC * GP * D];         // 16 x 17 x 32 = 34.8 KB

    int bid = blockIdx.x;
    const float* h; const float* ef; const int* srcA; const int* dstA;
    const int* bins; const int* bincnt; float* agg; int first, cap, bin;
    if (bid < NB_NET_NN) {
        bin = bid; first = bid * TSRC;
        h = net_feat; ef = pin_feat; srcA = pinned_src; dstA = pinned_dst;
        bins = g_bin_net; bincnt = g_bincnt_net; agg = g_agg_cell_pd; cap = CAPN;
    } else {
        bin = bid - NB_NET_NN; first = bin * TSRC;
        h = hanna_feat; ef = edge_feat; srcA = pf_src; dstA = pf_dst;
        bins = g_bin_han; bincnt = g_bincnt_han; agg = g_agg_cell_pf; cap = CAPH;
    }
    int tid = threadIdx.x;

    if (tid < TSRC * D) ((float*)sh_h4)[tid] = h[(size_t)first * D + tid];
    __syncthreads();

    // ---- phase 1: G compute (thread = (p, o), 16 accumulators) ----
    {
        int p = tid >> 5, o = tid & 31;
        const float* w = ((p < DPF) ? (W_topo + p * (D * D)) : b_topo) + o;
        float acc[TSRC];
#pragma unroll
        for (int t = 0; t < TSRC; t++) acc[t] = 0.f;
#pragma unroll
        for (int i4 = 0; i4 < 8; i4++) {
            float w0 = w[(i4 * 4 + 0) * D];
            float w1 = w[(i4 * 4 + 1) * D];
            float w2 = w[(i4 * 4 + 2) * D];
            float w3 = w[(i4 * 4 + 3) * D];
#pragma unroll
            for (int t = 0; t < TSRC; t++) {
                float4 h4 = sh_h4[t * 8 + i4];
                acc[t] = fmaf(h4.x, w0, fmaf(h4.y, w1, fmaf(h4.z, w2, fmaf(h4.w, w3, acc[t]))));
            }
        }
#pragma unroll
        for (int t = 0; t < TSRC; t++) sh_G[t * (GP * D) + p * D + o] = acc[t];
    }
    __syncthreads();

    // ---- phase 2: edge streaming from this block's bin ----
    int bs = bin * cap;
    int nE = bincnt[bin];
    int grp = tid >> 3;        // 68 groups of 8
    int j8 = tid & 7;
    int iters = (nE + 67) / 68;
    for (int it = 0; it < iters; it++) {
        int j = it * 68 + grp;
        bool valid = j < nE;
        int eid = bins[bs + (valid ? j : 0)];
        int s = srcA[eid];
        int t = s - first;
        int d = dstA[eid];
        float2 c2 = ((const float2*)(ef + (size_t)eid * DPF))[j8];
        const float* Gt = sh_G + t * (GP * D);
        float4 a = {0.f, 0.f, 0.f, 0.f};
#pragma unroll
        for (int p = 0; p < GP; p++) {
            float cp;
            if (p < DPF) cp = __shfl_sync(0xffffffffu, (p & 1) ? c2.y : c2.x, p >> 1, 8);
            else cp = 1.f;
            float4 g4 = ((const float4*)(Gt + p * D))[j8];
            a.x = fmaf(cp, g4.x, a.x);
            a.y = fmaf(cp, g4.y, a.y);
            a.z = fmaf(cp, g4.z, a.z);
            a.w = fmaf(cp, g4.w, a.w);
        }
        if (valid) red_add_f4(agg + (size_t)d * D + j8 * 4, a);
    }
}

// merged epilogue: block ranges dispatch cell / net / gcell outputs
#define NBF_CELL ((N_CELL * D) / 256)   // 6250
#define NBF_NET  (N_NET / 8)            // 1250
#define NBF_GC   (N_GCELL / 8)          // 2500
__global__ void k_final(const float* __restrict__ net_feat,
                        const float* __restrict__ W_pins, const float* __restrict__ b_pins,
                        const float* __restrict__ W_net, const float* __restrict__ b_net,
                        const float* __restrict__ W_connect, const float* __restrict__ b_connect,
                        const float* __restrict__ W_pt, const float* __restrict__ b_pt,
                        const float* __restrict__ b_pinned, const float* __restrict__ b_pf,
                        float* __restrict__ out_cell, float* __restrict__ out_net,
                        float* __restrict__ out_gcell) {
    __shared__ float sW1[D * D], sW2[D * D];
    int b = blockIdx.x;
    if (b < NBF_CELL) {
        int idx = b * 256 + threadIdx.x;
        int c = idx >> 5, o = idx & 31;
        float d1 = (float)max(g_cnt_pinned_dst[c], 1);
        float d2 = (float)max(g_cnt_pf_dst[c], 1);
        out_cell[idx] = g_agg_cell_pd[idx] / d1 + b_pinned[o]
                      + g_agg_cell_pf[idx] / d2 + b_pf[o];
        return;
    }
    if (b < NBF_CELL + NBF_NET) {
        for (int i = threadIdx.x; i < D * D; i += 256) { sW1[i] = W_pins[i]; sW2[i] = W_net[i]; }
        __syncthreads();
        int n = (b - NBF_CELL) * 8 + (threadIdx.x >> 5);
        int o = threadIdx.x & 31;
        float acc = 0.f, acc2 = 0.f;
#pragma unroll
        for (int i = 0; i < D; i++) {
            acc  = fmaf(g_agg_net[n * D + i], sW1[i * D + o], acc);
            acc2 = fmaf(net_feat[n * D + i],  sW2[i * D + o], acc2);
        }
        float ddn = rsqrtf((float)max(g_cnt_pins_dst[n], 1));
        out_net[n * D + o] = acc * ddn + b_pins[o] + acc2 + b_net[o];
        return;
    }
    {
        for (int i = threadIdx.x; i < D * D; i += 256) { sW1[i] = W_connect[i]; sW2[i] = W_pt[i]; }
        __syncthreads();
        int g = (b - NBF_CELL - NBF_NET) * 8 + (threadIdx.x >> 5);
        int o = threadIdx.x & 31;
        float acc = 0.f, acc2 = 0.f;
#pragma unroll
        for (int i = 0; i < D; i++) {
            acc  = fmaf(g_agg_gc_c[g * D + i],  sW1[i * D + o], acc);
            acc2 = fmaf(g_agg_gc_pt[g * D + i], sW2[i * D + o], acc2);
        }
        float dc = rsqrtf((float)max(g_cnt_connect_dst[g], 1));
        float dp = rsqrtf((float)max(g_cnt_pt_dst[g], 1));
        out_gcell[g * D + o] = acc * dc + b_connect[o] + acc2 * dp + b_pt[o];
    }
}

// ---------------- launch ----------------

extern "C" void kernel_launch(void* const* d_in, const int* in_sizes, int n_in,
                              void* d_out, int out_size) {
    const float* node_feat   = (const float*)d_in[0];
    const float* net_feat    = (const float*)d_in[1];
    const float* pin_feat    = (const float*)d_in[2];
    const float* hanna_feat  = (const float*)d_in[3];
    const float* edge_feat   = (const float*)d_in[4];
    const int* pins_src      = (const int*)d_in[5];
    const int* pins_dst      = (const int*)d_in[6];
    const int* pinned_src    = (const int*)d_in[7];
    const int* pinned_dst    = (const int*)d_in[8];
    const int* connect_src   = (const int*)d_in[9];
    const int* connect_dst   = (const int*)d_in[10];
    const int* pt_src        = (const int*)d_in[11];
    const int* pt_dst        = (const int*)d_in[12];
    const int* pf_src        = (const int*)d_in[13];
    const int* pf_dst        = (const int*)d_in[14];
    const float* W_net       = (const float*)d_in[15];
    const float* b_net       = (const float*)d_in[16];
    const float* W_topo      = (const float*)d_in[17];
    const float* b_topo      = (const float*)d_in[18];
    const float* W_pins      = (const float*)d_in[19];
    const float* b_pins      = (const float*)d_in[20];
    const float* W_connect   = (const float*)d_in[21];
    const float* b_connect   = (const float*)d_in[22];
    const float* W_pt        = (const float*)d_in[23];
    const float* b_pt        = (const float*)d_in[24];
    const float* b_pinned    = (const float*)d_in[25];
    const float* b_pf        = (const float*)d_in[26];

    float* out       = (float*)d_out;
    float* out_cell  = out;
    float* out_net   = out + (size_t)N_CELL * D;
    float* out_gcell = out + (size_t)(N_CELL + N_NET) * D;

    // side streams + events for fork/join inside graph capture (created once; never freed)
    static cudaStream_t s1 = nullptr, s2 = nullptr;
    static cudaEvent_t evZ = nullptr, evNN = nullptr, evDST = nullptr;
    if (s1 == nullptr) {
        cudaStreamCreateWithFlags(&s1, cudaStreamNonBlocking);
        cudaStreamCreateWithFlags(&s2, cudaStreamNonBlocking);
        cudaEventCreateWithFlags(&evZ, cudaEventDisableTiming);
        cudaEventCreateWithFlags(&evNN, cudaEventDisableTiming);
        cudaEventCreateWithFlags(&evDST, cudaEventDisableTiming);
    }

    // main: zero everything
    k_zero<<<1024, 256>>>();
    cudaEventRecord(evZ, 0);

    // s1: bins -> nnconv (no dependence on any degree counts)
    cudaStreamWaitEvent(s1, evZ, 0);
    k_fill_bins<<<(NE + 255) / 256, 256, 0, s1>>>(pinned_src, pf_src);
    k_nn<<<NB_NET_NN + NB_GC_NN, 544, 0, s1>>>(net_feat, hanna_feat, W_topo, b_topo,
                                               pin_feat, edge_feat,
                                               pinned_src, pinned_dst, pf_src, pf_dst);
    cudaEventRecord(evNN, s1);

    // s2: destination degrees (only k_final needs them)
    cudaStreamWaitEvent(s2, evZ, 0);
    k_deg_dst<<<(NE + 255) / 256, 256, 0, s2>>>(pins_dst, pinned_dst, connect_dst,
                                                pt_dst, pf_dst);
    cudaEventRecord(evDST, s2);

    // main: source degrees -> graphconv scatter (concurrent with s1/s2)
    k_deg_src<<<(NE + 255) / 256, 256>>>(pins_src, connect_src, pt_src);
    k_gc_scatter<<<(3 * NE * 8 + 255) / 256, 256>>>(node_feat, hanna_feat,
                                                    pins_src, pins_dst,
                                                    connect_src, connect_dst,
                                                    pt_src, pt_dst);

    // join and finish
    cudaStreamWaitEvent(0, evNN, 0);
    cudaStreamWaitEvent(0, evDST, 0);
    k_final<<<NBF_CELL + NBF_NET + NBF_GC, 256>>>(net_feat, W_pins, b_pins, W_net, b_net,
                                                  W_connect, b_connect, W_pt, b_pt,
                                                  b_pinned, b_pf,
                                                  out_cell, out_net, out_gcell);
}